// round 10
// baseline (speedup 1.0000x reference)
#include <cuda_runtime.h>

// ---------------------------------------------------------------------------
// RModel_29257317221019: fused cos-MLP deform (3->32->32->32->3) + trilinear
// sample from 256^3 volume.
// 1 point/thread, f32x2 over output pairs, ALL weights in __constant__
// (uniform constant-port loads). __launch_bounds__(128,5) -> 20 warps/SM.
// ---------------------------------------------------------------------------

typedef unsigned long long u64;

__device__ __forceinline__ void upk2(u64 v, float& lo, float& hi) {
    asm("mov.b64 {%0, %1}, %2;" : "=f"(lo), "=f"(hi) : "l"(v));
}
__device__ __forceinline__ u64 pk2(float lo, float hi) {
    u64 r; asm("mov.b64 %0, {%1, %2};" : "=l"(r) : "f"(lo), "f"(hi)); return r;
}
__device__ __forceinline__ u64 dup2(float v) {
    u64 r; asm("mov.b64 %0, {%1, %1};" : "=l"(r) : "f"(v)); return r;
}
__device__ __forceinline__ u64 ffma2(u64 a, u64 b, u64 c) {
    u64 r; asm("fma.rn.f32x2 %0, %1, %2, %3;" : "=l"(r) : "l"(a), "l"(b), "l"(c)); return r;
}

// Weights in constant memory (u64 = f32x2 operand pairs, raw layouts):
__constant__ u64 cW1[3][16];
__constant__ u64 cB1[16];
__constant__ u64 cW2[32][16];
__constant__ u64 cB2[16];
__constant__ u64 cW3[32][16];
__constant__ u64 cB3[16];
// Final layer, prepacked by prep_kernel:
//   cWfP[2k]   = (Wf[k][0], Wf[k][1]),  cWfP[2k+1] = (Wf[k][2], 0)
//   cWfP[64]   = (bf0, bf1),            cWfP[65]   = (bf2, 0)
__constant__ u64 cWfP[66];

__device__ u64 g_wf_scratch[66];

__global__ void prep_kernel(const float* __restrict__ Wf,
                            const float* __restrict__ bf) {
    int k = threadIdx.x;
    if (k < 32) {
        g_wf_scratch[2 * k]     = pk2(Wf[3 * k + 0], Wf[3 * k + 1]);
        g_wf_scratch[2 * k + 1] = pk2(Wf[3 * k + 2], 0.0f);
    }
    if (k == 0) {
        g_wf_scratch[64] = pk2(bf[0], bf[1]);
        g_wf_scratch[65] = pk2(bf[2], 0.0f);
    }
}

#define BLK 128

__global__ __launch_bounds__(BLK, 5)
void deform_sample_kernel(
    const float* __restrict__ x,
    const float* __restrict__ vol,
    float* __restrict__ out,
    int npts)
{
    int t = blockIdx.x * blockDim.x + threadIdx.x;
    if (t >= npts) return;

    // One point per thread (x layout: 4 floats/point, coords in [0:3])
    float4 X = reinterpret_cast<const float4*>(x)[t];

    float h[32];
    u64 a[16];

    // ---- Layer 1: h = cos(c @ W1 + b1) ----
    {
        u64 c0 = dup2(X.x), c1 = dup2(X.y), c2 = dup2(X.z);
#pragma unroll
        for (int q = 0; q < 8; q++) {           // d = 4q .. 4q+3  (j = 2q, 2q+1)
            u64 p0 = cB1[2 * q], p1 = cB1[2 * q + 1];
            p0 = ffma2(c0, cW1[0][2 * q],     p0);
            p1 = ffma2(c0, cW1[0][2 * q + 1], p1);
            p0 = ffma2(c1, cW1[1][2 * q],     p0);
            p1 = ffma2(c1, cW1[1][2 * q + 1], p1);
            p0 = ffma2(c2, cW1[2][2 * q],     p0);
            p1 = ffma2(c2, cW1[2][2 * q + 1], p1);
            float lo, hi;
            upk2(p0, lo, hi); h[4*q]   = __cosf(lo); h[4*q+1] = __cosf(hi);
            upk2(p1, lo, hi); h[4*q+2] = __cosf(lo); h[4*q+3] = __cosf(hi);
        }
    }

    // ---- Layer 2: h = cos(h @ W2 + b2) ----
#pragma unroll
    for (int j = 0; j < 16; j++) a[j] = cB2[j];
#pragma unroll
    for (int k = 0; k < 32; k++) {
        u64 d = dup2(h[k]);
#pragma unroll
        for (int j = 0; j < 16; j++) a[j] = ffma2(d, cW2[k][j], a[j]);
    }
#pragma unroll
    for (int p = 0; p < 16; p++) {
        float lo, hi; upk2(a[p], lo, hi);
        h[2*p] = __cosf(lo); h[2*p+1] = __cosf(hi);
    }

    // ---- Layer 3: h = cos(h @ W3 + b3) ----
#pragma unroll
    for (int j = 0; j < 16; j++) a[j] = cB3[j];
#pragma unroll
    for (int k = 0; k < 32; k++) {
        u64 d = dup2(h[k]);
#pragma unroll
        for (int j = 0; j < 16; j++) a[j] = ffma2(d, cW3[k][j], a[j]);
    }
#pragma unroll
    for (int p = 0; p < 16; p++) {
        float lo, hi; upk2(a[p], lo, hi);
        h[2*p] = __cosf(lo); h[2*p+1] = __cosf(hi);
    }

    // ---- Final: coord = c + 5 * (h @ Wf + bf), packed pairs ----
    float px, py, pz;
    {
        u64 e01 = cWfP[64], e2 = cWfP[65];
        u64 f01 = 0ull,     f2 = 0ull;      // second chain (0.0f pairs)
#pragma unroll
        for (int k = 0; k < 32; k += 2) {
            u64 d0 = dup2(h[k]);
            u64 d1 = dup2(h[k + 1]);
            e01 = ffma2(d0, cWfP[2 * k],     e01);
            e2  = ffma2(d0, cWfP[2 * k + 1], e2);
            f01 = ffma2(d1, cWfP[2 * k + 2], f01);
            f2  = ffma2(d1, cWfP[2 * k + 3], f2);
        }
        float e0a, e1a, e2a, f0a, f1a, f2a, jk;
        upk2(e01, e0a, e1a); upk2(e2, e2a, jk);
        upk2(f01, f0a, f1a); upk2(f2, f2a, jk);
        px = fmaf(5.0f, e0a + f0a, X.x);
        py = fmaf(5.0f, e1a + f1a, X.y);
        pz = fmaf(5.0f, e2a + f2a, X.z);
    }

    // ---- Trilinear sample ----
    float cx = fminf(fmaxf(px, 0.0f), 255.0f);
    float cy = fminf(fmaxf(py, 0.0f), 255.0f);
    float cz = fminf(fmaxf(pz, 0.0f), 255.0f);

    float fx0 = floorf(cx), fy0 = floorf(cy), fz0 = floorf(cz);
    int ix0 = (int)fx0, iy0 = (int)fy0, iz0 = (int)fz0;
    int ix1 = min(ix0 + 1, 255);
    int iy1 = min(iy0 + 1, 255);
    int iz1 = min(iz0 + 1, 255);

    float fx = cx - fx0, fy = cy - fy0, fz = cz - fz0;
    float gx = 1.0f - fx, gy = 1.0f - fy, gz = 1.0f - fz;

    int X0 = ix0 << 16, X1 = ix1 << 16;
    int Y0 = iy0 << 8,  Y1 = iy1 << 8;

    float v000 = __ldg(vol + (X0 + Y0 + iz0));
    float v100 = __ldg(vol + (X1 + Y0 + iz0));
    float v010 = __ldg(vol + (X0 + Y1 + iz0));
    float v001 = __ldg(vol + (X0 + Y0 + iz1));
    float v110 = __ldg(vol + (X1 + Y1 + iz0));
    float v101 = __ldg(vol + (X1 + Y0 + iz1));
    float v011 = __ldg(vol + (X0 + Y1 + iz1));
    float v111 = __ldg(vol + (X1 + Y1 + iz1));

    float r;
    r  = v000 * (gx * gy * gz);
    r += v100 * (fx * gy * gz);
    r += v010 * (gx * fy * gz);
    r += v001 * (gx * gy * fz);
    r += v110 * (fx * fy * gz);
    r += v101 * (fx * gy * fz);
    r += v011 * (gx * fy * fz);
    r += v111 * (fx * fy * fz);

    out[t] = r;
}

extern "C" void kernel_launch(void* const* d_in, const int* in_sizes, int n_in,
                              void* d_out, int out_size) {
    const float* x   = (const float*)d_in[0];
    const float* vol = (const float*)d_in[9];
    float* out = (float*)d_out;

    // Stage weights into constant memory (D2D memcpy nodes; capturable).
    cudaMemcpyToSymbolAsync(cW1, d_in[1], 3  * 32 * 4, 0, cudaMemcpyDeviceToDevice, 0);
    cudaMemcpyToSymbolAsync(cB1, d_in[2], 32 * 4,      0, cudaMemcpyDeviceToDevice, 0);
    cudaMemcpyToSymbolAsync(cW2, d_in[3], 32 * 32 * 4, 0, cudaMemcpyDeviceToDevice, 0);
    cudaMemcpyToSymbolAsync(cB2, d_in[4], 32 * 4,      0, cudaMemcpyDeviceToDevice, 0);
    cudaMemcpyToSymbolAsync(cW3, d_in[5], 32 * 32 * 4, 0, cudaMemcpyDeviceToDevice, 0);
    cudaMemcpyToSymbolAsync(cB3, d_in[6], 32 * 4,      0, cudaMemcpyDeviceToDevice, 0);

    // Prepack final-layer pairs on device, then stage into constant memory.
    prep_kernel<<<1, 32>>>((const float*)d_in[7], (const float*)d_in[8]);
    void* scratch_ptr = 0;
    cudaGetSymbolAddress(&scratch_ptr, g_wf_scratch);
    cudaMemcpyToSymbolAsync(cWfP, scratch_ptr, 66 * 8, 0, cudaMemcpyDeviceToDevice, 0);

    int npts = out_size;           // 2,097,152 points, 1 point/thread
    int grid = (npts + BLK - 1) / BLK;

    deform_sample_kernel<<<grid, BLK>>>(x, vol, out, npts);
}

// round 11
// speedup vs baseline: 1.0744x; 1.0744x over previous
#include <cuda_runtime.h>

// ---------------------------------------------------------------------------
// RModel_29257317221019: fused cos-MLP deform (3->32->32->32->3) + trilinear
// sample from 256^3 volume.
// 2 points/thread, f32x2 over output pairs, __launch_bounds__(128,4).
// Weight sourcing SPLIT across ports to relieve the constant port:
//   - j=0..7  of each W2/W3 row: __constant__  (LDC/LDCU, const port)
//   - j=8..15 of each W2/W3 row: shared memory (broadcast LDS.128, L1 port)
// Layer1 / biases / final layer stay constant (small traffic).
// ---------------------------------------------------------------------------

typedef unsigned long long u64;

__device__ __forceinline__ void upk2(u64 v, float& lo, float& hi) {
    asm("mov.b64 {%0, %1}, %2;" : "=f"(lo), "=f"(hi) : "l"(v));
}
__device__ __forceinline__ u64 pk2(float lo, float hi) {
    u64 r; asm("mov.b64 %0, {%1, %2};" : "=l"(r) : "f"(lo), "f"(hi)); return r;
}
__device__ __forceinline__ u64 dup2(float v) {
    u64 r; asm("mov.b64 %0, {%1, %1};" : "=l"(r) : "f"(v)); return r;
}
__device__ __forceinline__ u64 ffma2(u64 a, u64 b, u64 c) {
    u64 r; asm("fma.rn.f32x2 %0, %1, %2, %3;" : "=l"(r) : "l"(a), "l"(b), "l"(c)); return r;
}
__device__ __forceinline__ void lds_v2b64(unsigned addr, u64& a, u64& b) {
    asm("ld.shared.v2.b64 {%0, %1}, [%2];" : "=l"(a), "=l"(b) : "r"(addr));
}

// Constant half of weights (u64 = f32x2 operand pairs, raw layouts):
__constant__ u64 cW1[3][16];
__constant__ u64 cB1[16];
__constant__ u64 cW2[32][8];    // j = 0..7 only (lo half of each row)
__constant__ u64 cB2[16];
__constant__ u64 cW3[32][8];    // j = 0..7 only
__constant__ u64 cB3[16];
// Final layer, prepacked by prep_kernel:
//   cWfP[2k] = (Wf[k][0], Wf[k][1]), cWfP[2k+1] = (Wf[k][2], 0)
//   cWfP[64] = (bf0, bf1),           cWfP[65]   = (bf2, 0)
__constant__ u64 cWfP[66];

__device__ u64 g_scratch[2 * 32 * 8 + 66];   // [W2lo | W3lo | WfP]

__global__ void prep_kernel(const float* __restrict__ W2,
                            const float* __restrict__ W3,
                            const float* __restrict__ Wf,
                            const float* __restrict__ bf) {
    int i = threadIdx.x;                      // 256 threads
    // lo halves of W2/W3 rows as u64 pairs: row k floats [0..15] -> 8 u64
    {
        int k = i >> 3, m = i & 7;            // i = k*8+m, k<32
        const u64* w2u = reinterpret_cast<const u64*>(W2);
        const u64* w3u = reinterpret_cast<const u64*>(W3);
        g_scratch[i]       = w2u[k * 16 + m];
        g_scratch[256 + i] = w3u[k * 16 + m];
    }
    if (i < 32) {
        g_scratch[512 + 2 * i]     = pk2(Wf[3 * i + 0], Wf[3 * i + 1]);
        g_scratch[512 + 2 * i + 1] = pk2(Wf[3 * i + 2], 0.0f);
    }
    if (i == 0) {
        g_scratch[512 + 64] = pk2(bf[0], bf[1]);
        g_scratch[512 + 65] = pk2(bf[2], 0.0f);
    }
}

#define BLK 128

__global__ __launch_bounds__(BLK, 4)
void deform_sample_kernel(
    const float* __restrict__ x,
    const float* __restrict__ W2, const float* __restrict__ W3,
    const float* __restrict__ vol,
    float* __restrict__ out,
    int npairs)
{
    // Shared: hi halves (j=8..15) of W2/W3 rows, k-major: s[k][m], m=0..7
    __shared__ __align__(16) u64 sW2h[32 * 8];
    __shared__ __align__(16) u64 sW3h[32 * 8];
    {
        int tid = threadIdx.x;
        const u64* w2u = reinterpret_cast<const u64*>(W2);
        const u64* w3u = reinterpret_cast<const u64*>(W3);
#pragma unroll
        for (int r = 0; r < 2; r++) {
            int i = tid + r * BLK;            // 0..255
            int k = i >> 3, m = i & 7;
            sW2h[i] = w2u[k * 16 + 8 + m];    // floats 16..31 of row k
            sW3h[i] = w3u[k * 16 + 8 + m];
        }
    }
    __syncthreads();

    unsigned s2 = (unsigned)__cvta_generic_to_shared((void*)sW2h);
    unsigned s3 = (unsigned)__cvta_generic_to_shared((void*)sW3h);

    int t = blockIdx.x * blockDim.x + threadIdx.x;
    if (t >= npairs) return;

    // Two consecutive points (x layout: 4 floats/point, coords in [0:3])
    const float4* x4 = reinterpret_cast<const float4*>(x);
    float4 XA = x4[2 * t + 0];
    float4 XB = x4[2 * t + 1];

    float hA[32], hB[32];
    u64 aA[16], aB[16];

    // ---- Layer 1: h = cos(c @ W1 + b1) (constant) ----
    {
        u64 cA0 = dup2(XA.x), cA1 = dup2(XA.y), cA2 = dup2(XA.z);
        u64 cB0 = dup2(XB.x), cB1v = dup2(XB.y), cB2v = dup2(XB.z);
#pragma unroll
        for (int q = 0; q < 8; q++) {
            u64 b0 = cB1[2 * q], b1p = cB1[2 * q + 1];
            u64 pA0 = b0, pA1 = b1p, pB0 = b0, pB1 = b1p;
#pragma unroll
            for (int c = 0; c < 3; c++) {
                u64 w0 = cW1[c][2 * q];
                u64 w1p = cW1[c][2 * q + 1];
                u64 ca = (c == 0) ? cA0 : (c == 1) ? cA1 : cA2;
                u64 cb = (c == 0) ? cB0 : (c == 1) ? cB1v : cB2v;
                pA0 = ffma2(ca, w0, pA0);
                pA1 = ffma2(ca, w1p, pA1);
                pB0 = ffma2(cb, w0, pB0);
                pB1 = ffma2(cb, w1p, pB1);
            }
            float lo, hi;
            upk2(pA0, lo, hi); hA[4*q]   = __cosf(lo); hA[4*q+1] = __cosf(hi);
            upk2(pA1, lo, hi); hA[4*q+2] = __cosf(lo); hA[4*q+3] = __cosf(hi);
            upk2(pB0, lo, hi); hB[4*q]   = __cosf(lo); hB[4*q+1] = __cosf(hi);
            upk2(pB1, lo, hi); hB[4*q+2] = __cosf(lo); hB[4*q+3] = __cosf(hi);
        }
    }

    // ---- Layer 2: h = cos(h @ W2 + b2); lo half const, hi half smem ----
#pragma unroll
    for (int j = 0; j < 16; j++) { u64 b = cB2[j]; aA[j] = b; aB[j] = b; }
#pragma unroll
    for (int k = 0; k < 32; k++) {
        u64 dA = dup2(hA[k]);
        u64 dB = dup2(hB[k]);
#pragma unroll
        for (int j = 0; j < 8; j++) {
            u64 w = cW2[k][j];
            aA[j] = ffma2(dA, w, aA[j]);
            aB[j] = ffma2(dB, w, aB[j]);
        }
        unsigned row = s2 + k * 64;           // 8 u64 per row
#pragma unroll
        for (int m = 0; m < 4; m++) {
            u64 w0, w1;
            lds_v2b64(row + 16 * m, w0, w1);
            aA[8 + 2*m]     = ffma2(dA, w0, aA[8 + 2*m]);
            aA[8 + 2*m + 1] = ffma2(dA, w1, aA[8 + 2*m + 1]);
            aB[8 + 2*m]     = ffma2(dB, w0, aB[8 + 2*m]);
            aB[8 + 2*m + 1] = ffma2(dB, w1, aB[8 + 2*m + 1]);
        }
    }
#pragma unroll
    for (int p = 0; p < 16; p++) {
        float lo, hi;
        upk2(aA[p], lo, hi); hA[2*p] = __cosf(lo); hA[2*p+1] = __cosf(hi);
        upk2(aB[p], lo, hi); hB[2*p] = __cosf(lo); hB[2*p+1] = __cosf(hi);
    }

    // ---- Layer 3: h = cos(h @ W3 + b3); lo half const, hi half smem ----
#pragma unroll
    for (int j = 0; j < 16; j++) { u64 b = cB3[j]; aA[j] = b; aB[j] = b; }
#pragma unroll
    for (int k = 0; k < 32; k++) {
        u64 dA = dup2(hA[k]);
        u64 dB = dup2(hB[k]);
#pragma unroll
        for (int j = 0; j < 8; j++) {
            u64 w = cW3[k][j];
            aA[j] = ffma2(dA, w, aA[j]);
            aB[j] = ffma2(dB, w, aB[j]);
        }
        unsigned row = s3 + k * 64;
#pragma unroll
        for (int m = 0; m < 4; m++) {
            u64 w0, w1;
            lds_v2b64(row + 16 * m, w0, w1);
            aA[8 + 2*m]     = ffma2(dA, w0, aA[8 + 2*m]);
            aA[8 + 2*m + 1] = ffma2(dA, w1, aA[8 + 2*m + 1]);
            aB[8 + 2*m]     = ffma2(dB, w0, aB[8 + 2*m]);
            aB[8 + 2*m + 1] = ffma2(dB, w1, aB[8 + 2*m + 1]);
        }
    }
#pragma unroll
    for (int p = 0; p < 16; p++) {
        float lo, hi;
        upk2(aA[p], lo, hi); hA[2*p] = __cosf(lo); hA[2*p+1] = __cosf(hi);
        upk2(aB[p], lo, hi); hB[2*p] = __cosf(lo); hB[2*p+1] = __cosf(hi);
    }

    // ---- Final: coord = c + 5 * (h @ Wf + bf), packed pairs (constant) ----
    float pxy[2][3];
    {
        u64 eA01 = cWfP[64], eA2 = cWfP[65];
        u64 eB01 = eA01,     eB2 = eA2;
#pragma unroll
        for (int k = 0; k < 32; k++) {
            u64 w01 = cWfP[2 * k];
            u64 w2x = cWfP[2 * k + 1];
            u64 dA = dup2(hA[k]);
            u64 dB = dup2(hB[k]);
            eA01 = ffma2(dA, w01, eA01);
            eA2  = ffma2(dA, w2x, eA2);
            eB01 = ffma2(dB, w01, eB01);
            eB2  = ffma2(dB, w2x, eB2);
        }
        float f0, f1, f2, jk;
        upk2(eA01, f0, f1); upk2(eA2, f2, jk);
        pxy[0][0] = fmaf(5.0f, f0, XA.x);
        pxy[0][1] = fmaf(5.0f, f1, XA.y);
        pxy[0][2] = fmaf(5.0f, f2, XA.z);
        upk2(eB01, f0, f1); upk2(eB2, f2, jk);
        pxy[1][0] = fmaf(5.0f, f0, XB.x);
        pxy[1][1] = fmaf(5.0f, f1, XB.y);
        pxy[1][2] = fmaf(5.0f, f2, XB.z);
    }

    // ---- Trilinear sample (scalar per point) ----
    float res[2];
#pragma unroll
    for (int s = 0; s < 2; s++) {
        float cx = fminf(fmaxf(pxy[s][0], 0.0f), 255.0f);
        float cy = fminf(fmaxf(pxy[s][1], 0.0f), 255.0f);
        float cz = fminf(fmaxf(pxy[s][2], 0.0f), 255.0f);

        float fx0 = floorf(cx), fy0 = floorf(cy), fz0 = floorf(cz);
        int ix0 = (int)fx0, iy0 = (int)fy0, iz0 = (int)fz0;
        int ix1 = min(ix0 + 1, 255);
        int iy1 = min(iy0 + 1, 255);
        int iz1 = min(iz0 + 1, 255);

        float fx = cx - fx0, fy = cy - fy0, fz = cz - fz0;
        float gx = 1.0f - fx, gy = 1.0f - fy, gz = 1.0f - fz;

        int X0 = ix0 << 16, X1 = ix1 << 16;
        int Y0 = iy0 << 8,  Y1 = iy1 << 8;

        float v000 = __ldg(vol + (X0 + Y0 + iz0));
        float v100 = __ldg(vol + (X1 + Y0 + iz0));
        float v010 = __ldg(vol + (X0 + Y1 + iz0));
        float v001 = __ldg(vol + (X0 + Y0 + iz1));
        float v110 = __ldg(vol + (X1 + Y1 + iz0));
        float v101 = __ldg(vol + (X1 + Y0 + iz1));
        float v011 = __ldg(vol + (X0 + Y1 + iz1));
        float v111 = __ldg(vol + (X1 + Y1 + iz1));

        float r;
        r  = v000 * (gx * gy * gz);
        r += v100 * (fx * gy * gz);
        r += v010 * (gx * fy * gz);
        r += v001 * (gx * gy * fz);
        r += v110 * (fx * fy * gz);
        r += v101 * (fx * gy * fz);
        r += v011 * (gx * fy * fz);
        r += v111 * (fx * fy * fz);
        res[s] = r;
    }

    float2 o; o.x = res[0]; o.y = res[1];
    reinterpret_cast<float2*>(out)[t] = o;
}

extern "C" void kernel_launch(void* const* d_in, const int* in_sizes, int n_in,
                              void* d_out, int out_size) {
    const float* x   = (const float*)d_in[0];
    const float* W2g = (const float*)d_in[3];
    const float* W3g = (const float*)d_in[5];
    const float* vol = (const float*)d_in[9];
    float* out = (float*)d_out;

    // Stage constant halves (D2D memcpy nodes; capturable).
    cudaMemcpyToSymbolAsync(cW1, d_in[1], 3  * 32 * 4, 0, cudaMemcpyDeviceToDevice, 0);
    cudaMemcpyToSymbolAsync(cB1, d_in[2], 32 * 4,      0, cudaMemcpyDeviceToDevice, 0);
    cudaMemcpyToSymbolAsync(cB2, d_in[4], 32 * 4,      0, cudaMemcpyDeviceToDevice, 0);
    cudaMemcpyToSymbolAsync(cB3, d_in[6], 32 * 4,      0, cudaMemcpyDeviceToDevice, 0);

    // Prepack on device: W2/W3 lo halves + final-layer pairs -> constant.
    prep_kernel<<<1, 256>>>(W2g, W3g, (const float*)d_in[7], (const float*)d_in[8]);
    void* sp = 0;
    cudaGetSymbolAddress(&sp, g_scratch);
    cudaMemcpyToSymbolAsync(cW2,  sp,                         32 * 8 * 8, 0, cudaMemcpyDeviceToDevice, 0);
    cudaMemcpyToSymbolAsync(cW3,  (char*)sp + 256 * 8,        32 * 8 * 8, 0, cudaMemcpyDeviceToDevice, 0);
    cudaMemcpyToSymbolAsync(cWfP, (char*)sp + 512 * 8,        66 * 8,     0, cudaMemcpyDeviceToDevice, 0);

    int npts = out_size;           // 2,097,152 points
    int npairs = npts / 2;         // 2 points per thread
    int grid = (npairs + BLK - 1) / BLK;

    deform_sample_kernel<<<grid, BLK>>>(x, W2g, W3g, vol, out, npairs);
}

// round 12
// speedup vs baseline: 1.7088x; 1.5904x over previous
#include <cuda_runtime.h>

// ---------------------------------------------------------------------------
// RModel_29257317221019: fused cos-MLP deform (3->32->32->32->3) + trilinear
// sample from 256^3 volume.
// 2 points/thread, f32x2 over output pairs, __launch_bounds__(128,4).
// Port balancing WITHOUT intra-loop mixing (R11 lesson):
//   - Layer 1, Layer 2, final layer: __constant__, 16B LDC.128 reads
//   - Layer 3: weights in __shared__, broadcast LDS.128 reads only
// ---------------------------------------------------------------------------

typedef unsigned long long u64;

__device__ __forceinline__ void upk2(u64 v, float& lo, float& hi) {
    asm("mov.b64 {%0, %1}, %2;" : "=f"(lo), "=f"(hi) : "l"(v));
}
__device__ __forceinline__ u64 pk2(float lo, float hi) {
    u64 r; asm("mov.b64 %0, {%1, %2};" : "=l"(r) : "f"(lo), "f"(hi)); return r;
}
__device__ __forceinline__ u64 dup2(float v) {
    u64 r; asm("mov.b64 %0, {%1, %1};" : "=l"(r) : "f"(v)); return r;
}
__device__ __forceinline__ u64 ffma2(u64 a, u64 b, u64 c) {
    u64 r; asm("fma.rn.f32x2 %0, %1, %2, %3;" : "=l"(r) : "l"(a), "l"(b), "l"(c)); return r;
}

// Constant weights (u64 = f32x2 operand pairs, raw row-major layouts):
__constant__ __align__(16) u64 cW1[3][16];
__constant__ __align__(16) u64 cB1[16];
__constant__ __align__(16) u64 cW2[32][16];
__constant__ __align__(16) u64 cB2[16];
__constant__ __align__(16) u64 cB3[16];
// Final layer, prepacked by prep_kernel:
//   cWfP[2k] = (Wf[k][0], Wf[k][1]), cWfP[2k+1] = (Wf[k][2], 0)
//   cWfP[64] = (bf0, bf1),           cWfP[65]   = (bf2, 0)
__constant__ __align__(16) u64 cWfP[66];

__device__ u64 g_wf_scratch[66];

__global__ void prep_kernel(const float* __restrict__ Wf,
                            const float* __restrict__ bf) {
    int k = threadIdx.x;
    if (k < 32) {
        g_wf_scratch[2 * k]     = pk2(Wf[3 * k + 0], Wf[3 * k + 1]);
        g_wf_scratch[2 * k + 1] = pk2(Wf[3 * k + 2], 0.0f);
    }
    if (k == 0) {
        g_wf_scratch[64] = pk2(bf[0], bf[1]);
        g_wf_scratch[65] = pk2(bf[2], 0.0f);
    }
}

#define BLK 128

__global__ __launch_bounds__(BLK, 4)
void deform_sample_kernel(
    const float* __restrict__ x,
    const float* __restrict__ W3,
    const float* __restrict__ vol,
    float* __restrict__ out,
    int npairs)
{
    // Layer-3 weights in shared memory: 32 rows x 16 u64 (raw f32 pairs)
    __shared__ __align__(16) u64 sW3[32 * 16];
    {
        const u64* w3u = reinterpret_cast<const u64*>(W3);
        for (int i = threadIdx.x; i < 512; i += BLK) sW3[i] = w3u[i];
    }
    __syncthreads();
    const ulonglong2* sW3v = reinterpret_cast<const ulonglong2*>(sW3);

    int t = blockIdx.x * blockDim.x + threadIdx.x;
    if (t >= npairs) return;

    // Two consecutive points (x layout: 4 floats/point, coords in [0:3])
    const float4* x4 = reinterpret_cast<const float4*>(x);
    float4 XA = x4[2 * t + 0];
    float4 XB = x4[2 * t + 1];

    float hA[32], hB[32];
    u64 aA[16], aB[16];

    // ---- Layer 1: h = cos(c @ W1 + b1) (constant, 16B reads) ----
    {
        u64 cA0 = dup2(XA.x), cA1 = dup2(XA.y), cA2 = dup2(XA.z);
        u64 cB0 = dup2(XB.x), cB1v = dup2(XB.y), cB2v = dup2(XB.z);
        const ulonglong2* b1v = reinterpret_cast<const ulonglong2*>(cB1);
        const ulonglong2* w1v0 = reinterpret_cast<const ulonglong2*>(cW1[0]);
        const ulonglong2* w1v1 = reinterpret_cast<const ulonglong2*>(cW1[1]);
        const ulonglong2* w1v2 = reinterpret_cast<const ulonglong2*>(cW1[2]);
#pragma unroll
        for (int q = 0; q < 8; q++) {
            ulonglong2 bb = b1v[q];
            u64 pA0 = bb.x, pA1 = bb.y, pB0 = bb.x, pB1 = bb.y;
            ulonglong2 w0 = w1v0[q];
            ulonglong2 w1 = w1v1[q];
            ulonglong2 w2 = w1v2[q];
            pA0 = ffma2(cA0, w0.x, pA0);  pA1 = ffma2(cA0, w0.y, pA1);
            pB0 = ffma2(cB0, w0.x, pB0);  pB1 = ffma2(cB0, w0.y, pB1);
            pA0 = ffma2(cA1, w1.x, pA0);  pA1 = ffma2(cA1, w1.y, pA1);
            pB0 = ffma2(cB1v, w1.x, pB0); pB1 = ffma2(cB1v, w1.y, pB1);
            pA0 = ffma2(cA2, w2.x, pA0);  pA1 = ffma2(cA2, w2.y, pA1);
            pB0 = ffma2(cB2v, w2.x, pB0); pB1 = ffma2(cB2v, w2.y, pB1);
            float lo, hi;
            upk2(pA0, lo, hi); hA[4*q]   = __cosf(lo); hA[4*q+1] = __cosf(hi);
            upk2(pA1, lo, hi); hA[4*q+2] = __cosf(lo); hA[4*q+3] = __cosf(hi);
            upk2(pB0, lo, hi); hB[4*q]   = __cosf(lo); hB[4*q+1] = __cosf(hi);
            upk2(pB1, lo, hi); hB[4*q+2] = __cosf(lo); hB[4*q+3] = __cosf(hi);
        }
    }

    // ---- Layer 2: h = cos(h @ W2 + b2) (constant, 16B reads) ----
    {
        const ulonglong2* b2v = reinterpret_cast<const ulonglong2*>(cB2);
#pragma unroll
        for (int m = 0; m < 8; m++) {
            ulonglong2 b = b2v[m];
            aA[2*m] = b.x; aA[2*m+1] = b.y;
            aB[2*m] = b.x; aB[2*m+1] = b.y;
        }
    }
#pragma unroll
    for (int k = 0; k < 32; k++) {
        u64 dA = dup2(hA[k]);
        u64 dB = dup2(hB[k]);
        const ulonglong2* row = reinterpret_cast<const ulonglong2*>(cW2[k]);
#pragma unroll
        for (int m = 0; m < 8; m++) {
            ulonglong2 w = row[m];
            aA[2*m]   = ffma2(dA, w.x, aA[2*m]);
            aA[2*m+1] = ffma2(dA, w.y, aA[2*m+1]);
            aB[2*m]   = ffma2(dB, w.x, aB[2*m]);
            aB[2*m+1] = ffma2(dB, w.y, aB[2*m+1]);
        }
    }
#pragma unroll
    for (int p = 0; p < 16; p++) {
        float lo, hi;
        upk2(aA[p], lo, hi); hA[2*p] = __cosf(lo); hA[2*p+1] = __cosf(hi);
        upk2(aB[p], lo, hi); hB[2*p] = __cosf(lo); hB[2*p+1] = __cosf(hi);
    }

    // ---- Layer 3: h = cos(h @ W3 + b3) (shared only, LDS.128 reads) ----
    {
        const ulonglong2* b3v = reinterpret_cast<const ulonglong2*>(cB3);
#pragma unroll
        for (int m = 0; m < 8; m++) {
            ulonglong2 b = b3v[m];
            aA[2*m] = b.x; aA[2*m+1] = b.y;
            aB[2*m] = b.x; aB[2*m+1] = b.y;
        }
    }
#pragma unroll
    for (int k = 0; k < 32; k++) {
        u64 dA = dup2(hA[k]);
        u64 dB = dup2(hB[k]);
#pragma unroll
        for (int m = 0; m < 8; m++) {
            ulonglong2 w = sW3v[k * 8 + m];
            aA[2*m]   = ffma2(dA, w.x, aA[2*m]);
            aA[2*m+1] = ffma2(dA, w.y, aA[2*m+1]);
            aB[2*m]   = ffma2(dB, w.x, aB[2*m]);
            aB[2*m+1] = ffma2(dB, w.y, aB[2*m+1]);
        }
    }
#pragma unroll
    for (int p = 0; p < 16; p++) {
        float lo, hi;
        upk2(aA[p], lo, hi); hA[2*p] = __cosf(lo); hA[2*p+1] = __cosf(hi);
        upk2(aB[p], lo, hi); hB[2*p] = __cosf(lo); hB[2*p+1] = __cosf(hi);
    }

    // ---- Final: coord = c + 5 * (h @ Wf + bf) (constant, 16B reads) ----
    float pxy[2][3];
    {
        const ulonglong2* wfv = reinterpret_cast<const ulonglong2*>(cWfP);
        ulonglong2 bb = wfv[32];
        u64 eA01 = bb.x, eA2 = bb.y;
        u64 eB01 = bb.x, eB2 = bb.y;
#pragma unroll
        for (int k = 0; k < 32; k++) {
            ulonglong2 w = wfv[k];          // (w01, w2x)
            u64 dA = dup2(hA[k]);
            u64 dB = dup2(hB[k]);
            eA01 = ffma2(dA, w.x, eA01);
            eA2  = ffma2(dA, w.y, eA2);
            eB01 = ffma2(dB, w.x, eB01);
            eB2  = ffma2(dB, w.y, eB2);
        }
        float f0, f1, f2, jk;
        upk2(eA01, f0, f1); upk2(eA2, f2, jk);
        pxy[0][0] = fmaf(5.0f, f0, XA.x);
        pxy[0][1] = fmaf(5.0f, f1, XA.y);
        pxy[0][2] = fmaf(5.0f, f2, XA.z);
        upk2(eB01, f0, f1); upk2(eB2, f2, jk);
        pxy[1][0] = fmaf(5.0f, f0, XB.x);
        pxy[1][1] = fmaf(5.0f, f1, XB.y);
        pxy[1][2] = fmaf(5.0f, f2, XB.z);
    }

    // ---- Trilinear sample (scalar per point) ----
    float res[2];
#pragma unroll
    for (int s = 0; s < 2; s++) {
        float cx = fminf(fmaxf(pxy[s][0], 0.0f), 255.0f);
        float cy = fminf(fmaxf(pxy[s][1], 0.0f), 255.0f);
        float cz = fminf(fmaxf(pxy[s][2], 0.0f), 255.0f);

        float fx0 = floorf(cx), fy0 = floorf(cy), fz0 = floorf(cz);
        int ix0 = (int)fx0, iy0 = (int)fy0, iz0 = (int)fz0;
        int ix1 = min(ix0 + 1, 255);
        int iy1 = min(iy0 + 1, 255);
        int iz1 = min(iz0 + 1, 255);

        float fx = cx - fx0, fy = cy - fy0, fz = cz - fz0;
        float gx = 1.0f - fx, gy = 1.0f - fy, gz = 1.0f - fz;

        int X0 = ix0 << 16, X1 = ix1 << 16;
        int Y0 = iy0 << 8,  Y1 = iy1 << 8;

        float v000 = __ldg(vol + (X0 + Y0 + iz0));
        float v100 = __ldg(vol + (X1 + Y0 + iz0));
        float v010 = __ldg(vol + (X0 + Y1 + iz0));
        float v001 = __ldg(vol + (X0 + Y0 + iz1));
        float v110 = __ldg(vol + (X1 + Y1 + iz0));
        float v101 = __ldg(vol + (X1 + Y0 + iz1));
        float v011 = __ldg(vol + (X0 + Y1 + iz1));
        float v111 = __ldg(vol + (X1 + Y1 + iz1));

        float r;
        r  = v000 * (gx * gy * gz);
        r += v100 * (fx * gy * gz);
        r += v010 * (gx * fy * gz);
        r += v001 * (gx * gy * fz);
        r += v110 * (fx * fy * gz);
        r += v101 * (fx * gy * fz);
        r += v011 * (gx * fy * fz);
        r += v111 * (fx * fy * fz);
        res[s] = r;
    }

    float2 o; o.x = res[0]; o.y = res[1];
    reinterpret_cast<float2*>(out)[t] = o;
}

extern "C" void kernel_launch(void* const* d_in, const int* in_sizes, int n_in,
                              void* d_out, int out_size) {
    const float* x   = (const float*)d_in[0];
    const float* W3g = (const float*)d_in[5];
    const float* vol = (const float*)d_in[9];
    float* out = (float*)d_out;

    // Stage constant weights (D2D memcpy nodes; capturable).
    cudaMemcpyToSymbolAsync(cW1, d_in[1], 3  * 32 * 4, 0, cudaMemcpyDeviceToDevice, 0);
    cudaMemcpyToSymbolAsync(cB1, d_in[2], 32 * 4,      0, cudaMemcpyDeviceToDevice, 0);
    cudaMemcpyToSymbolAsync(cW2, d_in[3], 32 * 32 * 4, 0, cudaMemcpyDeviceToDevice, 0);
    cudaMemcpyToSymbolAsync(cB2, d_in[4], 32 * 4,      0, cudaMemcpyDeviceToDevice, 0);
    cudaMemcpyToSymbolAsync(cB3, d_in[6], 32 * 4,      0, cudaMemcpyDeviceToDevice, 0);

    // Prepack final-layer pairs on device, then stage into constant memory.
    prep_kernel<<<1, 32>>>((const float*)d_in[7], (const float*)d_in[8]);
    void* sp = 0;
    cudaGetSymbolAddress(&sp, g_wf_scratch);
    cudaMemcpyToSymbolAsync(cWfP, sp, 66 * 8, 0, cudaMemcpyDeviceToDevice, 0);

    int npts = out_size;           // 2,097,152 points
    int npairs = npts / 2;         // 2 points per thread
    int grid = (npairs + BLK - 1) / BLK;

    deform_sample_kernel<<<grid, BLK>>>(x, W3g, vol, out, npairs);
}

// round 13
// speedup vs baseline: 1.7113x; 1.0015x over previous
#include <cuda_runtime.h>

// ---------------------------------------------------------------------------
// RModel_29257317221019: fused cos-MLP deform (3->32->32->32->3) + trilinear
// sample from 256^3 volume.
// 2 points/thread, f32x2 over output pairs, __launch_bounds__(128,4).
// Port split with clean codegen:
//   - Layers 1, 2, final: __constant__, ulonglong2 -> LDC.128 (const port)
//   - Layer 3: __shared__ weights via inline-asm ld.shared.v2.b64
//     (register base + immediate offsets -> no IMAD, true LDS path)
// ---------------------------------------------------------------------------

typedef unsigned long long u64;

__device__ __forceinline__ void upk2(u64 v, float& lo, float& hi) {
    asm("mov.b64 {%0, %1}, %2;" : "=f"(lo), "=f"(hi) : "l"(v));
}
__device__ __forceinline__ u64 pk2(float lo, float hi) {
    u64 r; asm("mov.b64 %0, {%1, %2};" : "=l"(r) : "f"(lo), "f"(hi)); return r;
}
__device__ __forceinline__ u64 dup2(float v) {
    u64 r; asm("mov.b64 %0, {%1, %1};" : "=l"(r) : "f"(v)); return r;
}
__device__ __forceinline__ u64 ffma2(u64 a, u64 b, u64 c) {
    u64 r; asm("fma.rn.f32x2 %0, %1, %2, %3;" : "=l"(r) : "l"(a), "l"(b), "l"(c)); return r;
}
__device__ __forceinline__ void lds_v2b64(unsigned addr, u64& a, u64& b) {
    asm("ld.shared.v2.b64 {%0, %1}, [%2];" : "=l"(a), "=l"(b) : "r"(addr));
}

// Constant weights (u64 = f32x2 operand pairs, raw row-major layouts):
__constant__ __align__(16) u64 cW1[3][16];
__constant__ __align__(16) u64 cB1[16];
__constant__ __align__(16) u64 cW2[32][16];
__constant__ __align__(16) u64 cB2[16];
__constant__ __align__(16) u64 cB3[16];
// Final layer, prepacked by prep_kernel:
//   cWfP[2k] = (Wf[k][0], Wf[k][1]), cWfP[2k+1] = (Wf[k][2], 0)
//   cWfP[64] = (bf0, bf1),           cWfP[65]   = (bf2, 0)
__constant__ __align__(16) u64 cWfP[66];

__device__ u64 g_wf_scratch[66];

__global__ void prep_kernel(const float* __restrict__ Wf,
                            const float* __restrict__ bf) {
    int k = threadIdx.x;
    if (k < 32) {
        g_wf_scratch[2 * k]     = pk2(Wf[3 * k + 0], Wf[3 * k + 1]);
        g_wf_scratch[2 * k + 1] = pk2(Wf[3 * k + 2], 0.0f);
    }
    if (k == 0) {
        g_wf_scratch[64] = pk2(bf[0], bf[1]);
        g_wf_scratch[65] = pk2(bf[2], 0.0f);
    }
}

#define BLK 128

__global__ __launch_bounds__(BLK, 4)
void deform_sample_kernel(
    const float* __restrict__ x,
    const float* __restrict__ W3,
    const float* __restrict__ vol,
    float* __restrict__ out,
    int npairs)
{
    // Layer-3 weights in shared memory: raw row-major floats as 512 u64
    __shared__ __align__(16) u64 sW3[32 * 16];
    {
        const u64* w3u = reinterpret_cast<const u64*>(W3);
        for (int i = threadIdx.x; i < 512; i += BLK) sW3[i] = w3u[i];
    }
    __syncthreads();
    unsigned s3 = (unsigned)__cvta_generic_to_shared((void*)sW3);

    int t = blockIdx.x * blockDim.x + threadIdx.x;
    if (t >= npairs) return;

    // Two consecutive points (x layout: 4 floats/point, coords in [0:3])
    const float4* x4 = reinterpret_cast<const float4*>(x);
    float4 XA = x4[2 * t + 0];
    float4 XB = x4[2 * t + 1];

    float hA[32], hB[32];
    u64 aA[16], aB[16];

    // ---- Layer 1: h = cos(c @ W1 + b1) (constant, 16B LDC.128) ----
    {
        u64 cA0 = dup2(XA.x), cA1 = dup2(XA.y), cA2 = dup2(XA.z);
        u64 cB0 = dup2(XB.x), cB1v = dup2(XB.y), cB2v = dup2(XB.z);
        const ulonglong2* b1v  = reinterpret_cast<const ulonglong2*>(cB1);
        const ulonglong2* w1v0 = reinterpret_cast<const ulonglong2*>(cW1[0]);
        const ulonglong2* w1v1 = reinterpret_cast<const ulonglong2*>(cW1[1]);
        const ulonglong2* w1v2 = reinterpret_cast<const ulonglong2*>(cW1[2]);
#pragma unroll
        for (int q = 0; q < 8; q++) {
            ulonglong2 bb = b1v[q];
            u64 pA0 = bb.x, pA1 = bb.y, pB0 = bb.x, pB1 = bb.y;
            ulonglong2 w0 = w1v0[q];
            ulonglong2 w1 = w1v1[q];
            ulonglong2 w2 = w1v2[q];
            pA0 = ffma2(cA0, w0.x, pA0);  pA1 = ffma2(cA0, w0.y, pA1);
            pB0 = ffma2(cB0, w0.x, pB0);  pB1 = ffma2(cB0, w0.y, pB1);
            pA0 = ffma2(cA1, w1.x, pA0);  pA1 = ffma2(cA1, w1.y, pA1);
            pB0 = ffma2(cB1v, w1.x, pB0); pB1 = ffma2(cB1v, w1.y, pB1);
            pA0 = ffma2(cA2, w2.x, pA0);  pA1 = ffma2(cA2, w2.y, pA1);
            pB0 = ffma2(cB2v, w2.x, pB0); pB1 = ffma2(cB2v, w2.y, pB1);
            float lo, hi;
            upk2(pA0, lo, hi); hA[4*q]   = __cosf(lo); hA[4*q+1] = __cosf(hi);
            upk2(pA1, lo, hi); hA[4*q+2] = __cosf(lo); hA[4*q+3] = __cosf(hi);
            upk2(pB0, lo, hi); hB[4*q]   = __cosf(lo); hB[4*q+1] = __cosf(hi);
            upk2(pB1, lo, hi); hB[4*q+2] = __cosf(lo); hB[4*q+3] = __cosf(hi);
        }
    }

    // ---- Layer 2: h = cos(h @ W2 + b2) (constant, 16B LDC.128) ----
    {
        const ulonglong2* b2v = reinterpret_cast<const ulonglong2*>(cB2);
#pragma unroll
        for (int m = 0; m < 8; m++) {
            ulonglong2 b = b2v[m];
            aA[2*m] = b.x; aA[2*m+1] = b.y;
            aB[2*m] = b.x; aB[2*m+1] = b.y;
        }
    }
#pragma unroll
    for (int k = 0; k < 32; k++) {
        u64 dA = dup2(hA[k]);
        u64 dB = dup2(hB[k]);
        const ulonglong2* row = reinterpret_cast<const ulonglong2*>(cW2[k]);
#pragma unroll
        for (int m = 0; m < 8; m++) {
            ulonglong2 w = row[m];
            aA[2*m]   = ffma2(dA, w.x, aA[2*m]);
            aA[2*m+1] = ffma2(dA, w.y, aA[2*m+1]);
            aB[2*m]   = ffma2(dB, w.x, aB[2*m]);
            aB[2*m+1] = ffma2(dB, w.y, aB[2*m+1]);
        }
    }
#pragma unroll
    for (int p = 0; p < 16; p++) {
        float lo, hi;
        upk2(aA[p], lo, hi); hA[2*p] = __cosf(lo); hA[2*p+1] = __cosf(hi);
        upk2(aB[p], lo, hi); hB[2*p] = __cosf(lo); hB[2*p+1] = __cosf(hi);
    }

    // ---- Layer 3: h = cos(h @ W3 + b3) (shared, inline-asm LDS) ----
    {
        const ulonglong2* b3v = reinterpret_cast<const ulonglong2*>(cB3);
#pragma unroll
        for (int m = 0; m < 8; m++) {
            ulonglong2 b = b3v[m];
            aA[2*m] = b.x; aA[2*m+1] = b.y;
            aB[2*m] = b.x; aB[2*m+1] = b.y;
        }
    }
#pragma unroll
    for (int k = 0; k < 32; k++) {
        u64 dA = dup2(hA[k]);
        u64 dB = dup2(hB[k]);
#pragma unroll
        for (int m = 0; m < 4; m++) {
            u64 w0, w1;
            lds_v2b64(s3 + k * 128 + m * 32, w0, w1);       // j = 4m, 4m+1
            u64 w2, w3v;
            lds_v2b64(s3 + k * 128 + m * 32 + 16, w2, w3v); // j = 4m+2, 4m+3
            aA[4*m]   = ffma2(dA, w0, aA[4*m]);
            aA[4*m+1] = ffma2(dA, w1, aA[4*m+1]);
            aA[4*m+2] = ffma2(dA, w2, aA[4*m+2]);
            aA[4*m+3] = ffma2(dA, w3v, aA[4*m+3]);
            aB[4*m]   = ffma2(dB, w0, aB[4*m]);
            aB[4*m+1] = ffma2(dB, w1, aB[4*m+1]);
            aB[4*m+2] = ffma2(dB, w2, aB[4*m+2]);
            aB[4*m+3] = ffma2(dB, w3v, aB[4*m+3]);
        }
    }
#pragma unroll
    for (int p = 0; p < 16; p++) {
        float lo, hi;
        upk2(aA[p], lo, hi); hA[2*p] = __cosf(lo); hA[2*p+1] = __cosf(hi);
        upk2(aB[p], lo, hi); hB[2*p] = __cosf(lo); hB[2*p+1] = __cosf(hi);
    }

    // ---- Final: coord = c + 5 * (h @ Wf + bf) (constant, 16B LDC.128) ----
    float pxy[2][3];
    {
        const ulonglong2* wfv = reinterpret_cast<const ulonglong2*>(cWfP);
        ulonglong2 bb = wfv[32];
        u64 eA01 = bb.x, eA2 = bb.y;
        u64 eB01 = bb.x, eB2 = bb.y;
#pragma unroll
        for (int k = 0; k < 32; k++) {
            ulonglong2 w = wfv[k];          // (w01, w2x)
            u64 dA = dup2(hA[k]);
            u64 dB = dup2(hB[k]);
            eA01 = ffma2(dA, w.x, eA01);
            eA2  = ffma2(dA, w.y, eA2);
            eB01 = ffma2(dB, w.x, eB01);
            eB2  = ffma2(dB, w.y, eB2);
        }
        float f0, f1, f2, jk;
        upk2(eA01, f0, f1); upk2(eA2, f2, jk);
        pxy[0][0] = fmaf(5.0f, f0, XA.x);
        pxy[0][1] = fmaf(5.0f, f1, XA.y);
        pxy[0][2] = fmaf(5.0f, f2, XA.z);
        upk2(eB01, f0, f1); upk2(eB2, f2, jk);
        pxy[1][0] = fmaf(5.0f, f0, XB.x);
        pxy[1][1] = fmaf(5.0f, f1, XB.y);
        pxy[1][2] = fmaf(5.0f, f2, XB.z);
    }

    // ---- Trilinear sample (scalar per point) ----
    float res[2];
#pragma unroll
    for (int s = 0; s < 2; s++) {
        float cx = fminf(fmaxf(pxy[s][0], 0.0f), 255.0f);
        float cy = fminf(fmaxf(pxy[s][1], 0.0f), 255.0f);
        float cz = fminf(fmaxf(pxy[s][2], 0.0f), 255.0f);

        float fx0 = floorf(cx), fy0 = floorf(cy), fz0 = floorf(cz);
        int ix0 = (int)fx0, iy0 = (int)fy0, iz0 = (int)fz0;
        int ix1 = min(ix0 + 1, 255);
        int iy1 = min(iy0 + 1, 255);
        int iz1 = min(iz0 + 1, 255);

        float fx = cx - fx0, fy = cy - fy0, fz = cz - fz0;
        float gx = 1.0f - fx, gy = 1.0f - fy, gz = 1.0f - fz;

        int X0 = ix0 << 16, X1 = ix1 << 16;
        int Y0 = iy0 << 8,  Y1 = iy1 << 8;

        float v000 = __ldg(vol + (X0 + Y0 + iz0));
        float v100 = __ldg(vol + (X1 + Y0 + iz0));
        float v010 = __ldg(vol + (X0 + Y1 + iz0));
        float v001 = __ldg(vol + (X0 + Y0 + iz1));
        float v110 = __ldg(vol + (X1 + Y1 + iz0));
        float v101 = __ldg(vol + (X1 + Y0 + iz1));
        float v011 = __ldg(vol + (X0 + Y1 + iz1));
        float v111 = __ldg(vol + (X1 + Y1 + iz1));

        float r;
        r  = v000 * (gx * gy * gz);
        r += v100 * (fx * gy * gz);
        r += v010 * (gx * fy * gz);
        r += v001 * (gx * gy * fz);
        r += v110 * (fx * fy * gz);
        r += v101 * (fx * gy * fz);
        r += v011 * (gx * fy * fz);
        r += v111 * (fx * fy * fz);
        res[s] = r;
    }

    float2 o; o.x = res[0]; o.y = res[1];
    reinterpret_cast<float2*>(out)[t] = o;
}

extern "C" void kernel_launch(void* const* d_in, const int* in_sizes, int n_in,
                              void* d_out, int out_size) {
    const float* x   = (const float*)d_in[0];
    const float* W3g = (const float*)d_in[5];
    const float* vol = (const float*)d_in[9];
    float* out = (float*)d_out;

    // Stage constant weights (D2D memcpy nodes; capturable).
    cudaMemcpyToSymbolAsync(cW1, d_in[1], 3  * 32 * 4, 0, cudaMemcpyDeviceToDevice, 0);
    cudaMemcpyToSymbolAsync(cB1, d_in[2], 32 * 4,      0, cudaMemcpyDeviceToDevice, 0);
    cudaMemcpyToSymbolAsync(cW2, d_in[3], 32 * 32 * 4, 0, cudaMemcpyDeviceToDevice, 0);
    cudaMemcpyToSymbolAsync(cB2, d_in[4], 32 * 4,      0, cudaMemcpyDeviceToDevice, 0);
    cudaMemcpyToSymbolAsync(cB3, d_in[6], 32 * 4,      0, cudaMemcpyDeviceToDevice, 0);

    // Prepack final-layer pairs on device, then stage into constant memory.
    prep_kernel<<<1, 32>>>((const float*)d_in[7], (const float*)d_in[8]);
    void* sp = 0;
    cudaGetSymbolAddress(&sp, g_wf_scratch);
    cudaMemcpyToSymbolAsync(cWfP, sp, 66 * 8, 0, cudaMemcpyDeviceToDevice, 0);

    int npts = out_size;           // 2,097,152 points
    int npairs = npts / 2;         // 2 points per thread
    int grid = (npairs + BLK - 1) / BLK;

    deform_sample_kernel<<<grid, BLK>>>(x, W3g, vol, out, npairs);
}